// round 4
// baseline (speedup 1.0000x reference)
#include <cuda_runtime.h>
#include <math.h>

#define BB 4
#define TT 8192
#define DIMV 512
#define HH 8
#define DDIM 64
#define CCH 64
#define NCH 128          // TT / CCH
#define BHX 32           // BB * HH
#define RMS_EPS 1.1920929e-07f
#define MAXLR 0.01f

// ---------------- scratch (device globals: no allocation) ----------------
__device__ float g_s[(size_t)BB*TT*DIMV];          // rmsnorm(seq)
__device__ float g_k[(size_t)BHX*TT*DDIM];         // keys,  head-split (bh, t, d)
__device__ float g_v[(size_t)BHX*TT*DDIM];         // values
__device__ float g_q[(size_t)BHX*TT*DDIM];         // queries (shifted)
__device__ float g_u1[(size_t)BHX*NCH*DDIM*DDIM];  // surprises -> updates (in place)
__device__ float g_u2[(size_t)BHX*NCH*DDIM*DDIM];
__device__ float g_vals[(size_t)BB*TT*DIMV];       // merged-head retrieve output
__device__ float g_lr[BHX*TT];
__device__ float g_gate[BHX*TT];
__device__ float g_mom[BHX*NCH];
__device__ float g_dec[BHX*NCH];

__device__ __forceinline__ float sigmf(float x){ return 1.0f/(1.0f+expf(-x)); }

// ---------------- K1: per-token rmsnorm (also zero output pad rows) -------
__global__ void k_rmsnorm(const float* __restrict__ seq, float* __restrict__ outp){
    int tok = blockIdx.x;            // 0..B*T-1
    int tid = threadIdx.x;           // 128
    float4 x = ((const float4*)(seq + (size_t)tok*DIMV))[tid];
    float ss = x.x*x.x + x.y*x.y + x.z*x.z + x.w*x.w;
    #pragma unroll
    for (int o=16;o>0;o>>=1) ss += __shfl_xor_sync(0xffffffffu, ss, o);
    __shared__ float ws[4];
    if ((tid&31)==0) ws[tid>>5] = ss;
    __syncthreads();
    float tot = ws[0]+ws[1]+ws[2]+ws[3];
    float sc = rsqrtf(tot*(1.0f/DIMV) + RMS_EPS);
    float4 y = make_float4(x.x*sc, x.y*sc, x.z*sc, x.w*sc);
    ((float4*)(g_s + (size_t)tok*DIMV))[tid] = y;
    int tpos = tok & (TT-1);
    if (tpos < CCH-1)                // out rows shifted by c-1 start as zeros
        ((float4*)(outp + (size_t)tok*DIMV))[tid] = make_float4(0,0,0,0);
}

// ---------------- K1b: per-token lr (Wstep) and gate (Wgate, shifted) -----
__global__ void __launch_bounds__(256)
k_lr_gate(const float* __restrict__ Wstep, const float* __restrict__ Wgate){
    __shared__ float sWs[HH*DIMV];   // transposed [h][dd]
    __shared__ float sWg[HH*DIMV];
    int tid = threadIdx.x;
    for (int i=tid; i<HH*DIMV; i+=256){
        int h = i >> 9, dd = i & (DIMV-1);
        sWs[i] = Wstep[dd*HH + h];
        sWg[i] = Wgate[dd*HH + h];
    }
    __syncthreads();
    int warp = tid >> 5, lane = tid & 31;
    for (int it=0; it<16; it++){
        int tok = blockIdx.x*128 + warp*16 + it;   // 0..B*T-1
        int bi = tok >> 13, tpos = tok & (TT-1);
        const float* srow = g_s + (size_t)tok*DIMV;
        float aS[8], aG[8];
        #pragma unroll
        for (int h=0;h<8;h++){ aS[h]=0.f; aG[h]=0.f; }
        for (int i=0;i<16;i++){
            int dd = lane + 32*i;
            float v = srow[dd];
            #pragma unroll
            for (int h=0;h<8;h++){
                aS[h] += v * sWs[h*DIMV+dd];
                aG[h] += v * sWg[h*DIMV+dd];
            }
        }
        #pragma unroll
        for (int h=0;h<8;h++){
            #pragma unroll
            for (int o=16;o>0;o>>=1){
                aS[h] += __shfl_xor_sync(0xffffffffu, aS[h], o);
                aG[h] += __shfl_xor_sync(0xffffffffu, aG[h], o);
            }
        }
        if (lane < 8){
            int h = lane;
            size_t base = (size_t)(bi*HH + h)*TT;
            g_lr[base + tpos] = sigmf(aS[h]) * MAXLR;
            int j = tpos - (CCH-1);
            if (j >= 0) g_gate[base + j] = sigmf(aG[h]);
            if (tpos < CCH-1) g_gate[base + (TT-(CCH-1)+tpos)] = 0.5f; // padded rows
        }
    }
}

// ---------------- K2: per-chunk mean -> momentum / decay gates ------------
__global__ void __launch_bounds__(256)
k_chunk_gates(const float* __restrict__ Wmom, const float* __restrict__ Wdec){
    __shared__ float sc[DIMV];
    int blk = blockIdx.x;              // B*NCH
    int bi = blk / NCH, ch = blk % NCH;
    int tid = threadIdx.x;
    const float* base = g_s + ((size_t)(bi*TT + ch*CCH))*DIMV;
    float a0=0.f, a1=0.f;
    for (int tk=0;tk<CCH;tk++){
        a0 += base[(size_t)tk*DIMV + tid];
        a1 += base[(size_t)tk*DIMV + tid + 256];
    }
    sc[tid]     = a0*(1.0f/CCH);
    sc[tid+256] = a1*(1.0f/CCH);
    __syncthreads();
    if (tid < 32){
        int lane = tid;
        float am[8], ad[8];
        #pragma unroll
        for (int h=0;h<8;h++){ am[h]=0.f; ad[h]=0.f; }
        for (int i=0;i<16;i++){
            int dd = lane + 32*i;
            float v = sc[dd];
            #pragma unroll
            for (int h=0;h<8;h++){
                am[h] += v*Wmom[dd*HH+h];
                ad[h] += v*Wdec[dd*HH+h];
            }
        }
        #pragma unroll
        for (int h=0;h<8;h++){
            #pragma unroll
            for (int o=16;o>0;o>>=1){
                am[h] += __shfl_xor_sync(0xffffffffu, am[h], o);
                ad[h] += __shfl_xor_sync(0xffffffffu, ad[h], o);
            }
        }
        if (lane < 8){
            g_mom[(bi*HH+lane)*NCH + ch] = sigmf(am[lane]);
            g_dec[(bi*HH+lane)*NCH + ch] = sigmf(ad[lane]);
        }
    }
}

// ---------------- big SGEMM: 128x128 tile, 8x8 micro-tile -----------------
// MODE 0: A = g_s,  B = Wkv (N=1024), store split k/v head-layout
// MODE 1: A = g_s shifted +63 (zero pad), B = Wq (N=512), store q head-layout
// MODE 2: A = g_vals, B = Wcombine (N=512), store d_out at row jj+63
template<int MODE>
__global__ void __launch_bounds__(256)
k_sgemm(const float* __restrict__ Bm, float* __restrict__ Co, int Kd, int Nd){
    __shared__ float As[8][128];
    __shared__ float Bs[8][128];
    int tid = threadIdx.x;
    const int rowbase = blockIdx.y*128;
    const int colbase = blockIdx.x*128;
    const int arow = tid >> 1;
    const int acol = (tid & 1)*4;
    int grow = rowbase + arow;
    const float* aptr;
    bool avalid = true;
    if (MODE == 1){
        int bi = grow >> 13, jj = grow & (TT-1);
        int sj = jj + (CCH-1);
        avalid = (sj < TT);
        aptr = g_s + ((size_t)bi*TT + (avalid ? sj : 0))*DIMV;
    } else if (MODE == 0){
        aptr = g_s + (size_t)grow*DIMV;
    } else {
        aptr = g_vals + (size_t)grow*DIMV;
    }
    const int brow = tid >> 5;
    const int bcol = (tid & 31)*4;
    const float* bbase = Bm + colbase + bcol;

    float4 ra = avalid ? *(const float4*)(aptr + acol) : make_float4(0,0,0,0);
    float4 rb = *(const float4*)(bbase + (size_t)brow*Nd);

    const int tx = tid & 15, ty = tid >> 4;
    float acc[8][8];
    #pragma unroll
    for (int i=0;i<8;i++)
        #pragma unroll
        for (int j=0;j<8;j++) acc[i][j]=0.f;

    for (int k0=0; k0<Kd; k0+=8){
        As[acol+0][arow]=ra.x; As[acol+1][arow]=ra.y;
        As[acol+2][arow]=ra.z; As[acol+3][arow]=ra.w;
        *(float4*)(&Bs[brow][bcol]) = rb;
        __syncthreads();
        float4 na = make_float4(0,0,0,0), nb = na;
        if (k0+8 < Kd){
            na = avalid ? *(const float4*)(aptr + k0+8 + acol) : make_float4(0,0,0,0);
            nb = *(const float4*)(bbase + (size_t)(k0+8+brow)*Nd);
        }
        #pragma unroll
        for (int kk=0;kk<8;kk++){
            float4 a0 = *(const float4*)(&As[kk][ty*8]);
            float4 a1 = *(const float4*)(&As[kk][ty*8+4]);
            float4 b0 = *(const float4*)(&Bs[kk][tx*8]);
            float4 b1 = *(const float4*)(&Bs[kk][tx*8+4]);
            float av[8] = {a0.x,a0.y,a0.z,a0.w,a1.x,a1.y,a1.z,a1.w};
            float bv[8] = {b0.x,b0.y,b0.z,b0.w,b1.x,b1.y,b1.z,b1.w};
            #pragma unroll
            for (int i=0;i<8;i++)
                #pragma unroll
                for (int j=0;j<8;j++) acc[i][j] += av[i]*bv[j];
        }
        __syncthreads();
        ra = na; rb = nb;
    }

    #pragma unroll
    for (int i=0;i<8;i++){
        int r = rowbase + ty*8 + i;
        int bi = r >> 13, jj = r & (TT-1);
        #pragma unroll
        for (int jq=0;jq<2;jq++){
            int c = colbase + tx*8 + jq*4;
            float4 v = make_float4(acc[i][jq*4+0], acc[i][jq*4+1],
                                   acc[i][jq*4+2], acc[i][jq*4+3]);
            if (MODE == 0){
                float* dst; int e = c;
                if (e < HH*DDIM){ dst = g_k; } else { dst = g_v; e -= HH*DDIM; }
                int h = e / DDIM, dd0 = e & (DDIM-1);
                *(float4*)(dst + (((size_t)(bi*HH+h)*TT + jj))*DDIM + dd0) = v;
            } else if (MODE == 1){
                int h = c / DDIM, dd0 = c & (DDIM-1);
                *(float4*)(g_q + (((size_t)(bi*HH+h)*TT + jj))*DDIM + dd0) = v;
            } else {
                int dr = jj + (CCH-1);
                if (dr < TT)
                    *(float4*)(Co + ((size_t)(bi*TT+dr))*DIMV + c) = v;
            }
        }
    }
}

// ---------------- K5: per-chunk MLP forward + backward (surprises) --------
__global__ void __launch_bounds__(256)
k_grads(const float* __restrict__ w1, const float* __restrict__ w2){
    extern __shared__ float smem[];
    const int P = 65;
    float* sk = smem;
    float* sA = smem + 1*64*P;   // w1 then dx
    float* sB = smem + 2*64*P;   // w2
    float* sx = smem + 3*64*P;   // preactivation
    float* sh = smem + 4*64*P;   // silu(x)
    float* sG = smem + 5*64*P;   // dL/dy
    int blk = blockIdx.x;                    // bh*NCH + ch
    int bh = blk >> 7, ch = blk & (NCH-1);
    int tid = threadIdx.x;
    const float* kc  = g_k  + ((size_t)bh*TT + ch*CCH)*DDIM;
    const float* vc  = g_v  + ((size_t)bh*TT + ch*CCH)*DDIM;
    const float* lrc = g_lr + (size_t)bh*TT + ch*CCH;
    for (int i=tid;i<4096;i+=256){
        int r=i>>6, c=i&63;
        sk[r*P+c]=kc[i]; sA[r*P+c]=w1[i]; sB[r*P+c]=w2[i];
    }
    __syncthreads();
    const int tx=tid&15, ty=tid>>4;
    const int r0=ty*4, c0=tx*4;
    float acc[4][4];

    // GEMM1: x = k @ w1 ; h = silu(x)
    #pragma unroll
    for(int i=0;i<4;i++) for(int j=0;j<4;j++) acc[i][j]=0.f;
    for (int kk=0;kk<64;kk++){
        float a[4],b[4];
        #pragma unroll
        for(int i=0;i<4;i++) a[i]=sk[(r0+i)*P+kk];
        #pragma unroll
        for(int j=0;j<4;j++) b[j]=sA[kk*P+c0+j];
        #pragma unroll
        for(int i=0;i<4;i++) for(int j=0;j<4;j++) acc[i][j]+=a[i]*b[j];
    }
    #pragma unroll
    for(int i=0;i<4;i++) for(int j=0;j<4;j++){
        float z=acc[i][j];
        sx[(r0+i)*P+c0+j]=z;
        sh[(r0+i)*P+c0+j]=z*sigmf(z);
    }
    __syncthreads();

    // GEMM2: y = h @ w2 ; G = (2/d)*lr*(y-v)
    #pragma unroll
    for(int i=0;i<4;i++) for(int j=0;j<4;j++) acc[i][j]=0.f;
    for (int kk=0;kk<64;kk++){
        float a[4],b[4];
        #pragma unroll
        for(int i=0;i<4;i++) a[i]=sh[(r0+i)*P+kk];
        #pragma unroll
        for(int j=0;j<4;j++) b[j]=sB[kk*P+c0+j];
        #pragma unroll
        for(int i=0;i<4;i++) for(int j=0;j<4;j++) acc[i][j]+=a[i]*b[j];
    }
    #pragma unroll
    for(int i=0;i<4;i++){
        float lrv = lrc[r0+i];
        #pragma unroll
        for(int j=0;j<4;j++){
            float e = acc[i][j] - vc[(r0+i)*64 + c0+j];
            sG[(r0+i)*P+c0+j] = (2.0f/DDIM)*lrv*e;
        }
    }
    __syncthreads();

    // GEMM3: dh = G @ w2^T ; dx = dh * silu'(x)   (into sA)
    #pragma unroll
    for(int i=0;i<4;i++) for(int j=0;j<4;j++) acc[i][j]=0.f;
    for (int kk=0;kk<64;kk++){
        float a[4],b[4];
        #pragma unroll
        for(int i=0;i<4;i++) a[i]=sG[(r0+i)*P+kk];
        #pragma unroll
        for(int j=0;j<4;j++) b[j]=sB[(c0+j)*P+kk];
        #pragma unroll
        for(int i=0;i<4;i++) for(int j=0;j<4;j++) acc[i][j]+=a[i]*b[j];
    }
    __syncthreads();            // old sA (w1) reads finished; make write safe
    #pragma unroll
    for(int i=0;i<4;i++) for(int j=0;j<4;j++){
        float z = sx[(r0+i)*P+c0+j];
        float sg = sigmf(z);
        float ds = sg*(1.0f + z*(1.0f-sg));
        sA[(r0+i)*P+c0+j] = acc[i][j]*ds;
    }
    __syncthreads();

    // GEMM4: surprise1 = -(k^T @ dx)
    #pragma unroll
    for(int i=0;i<4;i++) for(int j=0;j<4;j++) acc[i][j]=0.f;
    for (int kk=0;kk<64;kk++){
        float a[4],b[4];
        #pragma unroll
        for(int i=0;i<4;i++) a[i]=sk[kk*P+r0+i];
        #pragma unroll
        for(int j=0;j<4;j++) b[j]=sA[kk*P+c0+j];
        #pragma unroll
        for(int i=0;i<4;i++) for(int j=0;j<4;j++) acc[i][j]+=a[i]*b[j];
    }
    float* o1 = g_u1 + (size_t)blk*4096;
    #pragma unroll
    for(int i=0;i<4;i++)
        *(float4*)(o1 + (r0+i)*64 + c0) =
            make_float4(-acc[i][0],-acc[i][1],-acc[i][2],-acc[i][3]);

    // GEMM5: surprise2 = -(h^T @ G)
    #pragma unroll
    for(int i=0;i<4;i++) for(int j=0;j<4;j++) acc[i][j]=0.f;
    for (int kk=0;kk<64;kk++){
        float a[4],b[4];
        #pragma unroll
        for(int i=0;i<4;i++) a[i]=sh[kk*P+r0+i];
        #pragma unroll
        for(int j=0;j<4;j++) b[j]=sG[kk*P+c0+j];
        #pragma unroll
        for(int i=0;i<4;i++) for(int j=0;j<4;j++) acc[i][j]+=a[i]*b[j];
    }
    float* o2 = g_u2 + (size_t)blk*4096;
    #pragma unroll
    for(int i=0;i<4;i++)
        *(float4*)(o2 + (r0+i)*64 + c0) =
            make_float4(-acc[i][0],-acc[i][1],-acc[i][2],-acc[i][3]);
}

// ---------------- K6: double first-order scan over chunks (in place) ------
__global__ void __launch_bounds__(256)
k_scan(){
    int bh = blockIdx.x;
    int idx = blockIdx.y*256 + threadIdx.x;      // 0..4095
    __shared__ float smg[NCH], sdc[NCH];
    if (threadIdx.x < NCH){
        smg[threadIdx.x] = g_mom[bh*NCH + threadIdx.x];
        sdc[threadIdx.x] = 1.0f - g_dec[bh*NCH + threadIdx.x];
    }
    __syncthreads();
    float m1=0.f,u1=0.f,m2=0.f,u2=0.f;
    size_t base = (size_t)bh*NCH*4096 + idx;
    for (int ch=0; ch<NCH; ch++){
        size_t off = base + (size_t)ch*4096;
        float f1 = g_u1[off];
        float f2 = g_u2[off];
        float mg = smg[ch], dk = sdc[ch];
        m1 = mg*m1 + f1;  u1 = dk*u1 + m1;
        m2 = mg*m2 + f2;  u2 = dk*u2 + m2;
        g_u1[off] = u1;
        g_u2[off] = u2;
    }
}

// ---------------- K7: retrieve MLP + multihead rmsnorm + gate -------------
__global__ void __launch_bounds__(256)
k_retrieve(const float* __restrict__ w1, const float* __restrict__ w2,
           const float* __restrict__ gamma){
    extern __shared__ float smem[];
    const int P = 65;
    float* sq = smem;
    float* sW = smem + 1*64*P;
    float* sh = smem + 2*64*P;
    float* sy = smem + 3*64*P;
    int blk = blockIdx.x;
    int bh = blk >> 7, ch = blk & (NCH-1);
    int bi = bh >> 3, h = bh & 7;
    int tid = threadIdx.x;
    const float* qc = g_q  + ((size_t)bh*TT + ch*CCH)*DDIM;
    const float* u1 = g_u1 + (size_t)blk*4096;
    const float* u2 = g_u2 + (size_t)blk*4096;
    for (int i=tid;i<4096;i+=256){
        int r=i>>6, c=i&63;
        sq[r*P+c]=qc[i];
        sW[r*P+c]=w1[i]+u1[i];
    }
    __syncthreads();
    const int tx=tid&15, ty=tid>>4;
    const int r0=ty*4, c0=tx*4;
    float acc[4][4];

    // x = q @ (w1+u1) ; h = silu(x)
    #pragma unroll
    for(int i=0;i<4;i++) for(int j=0;j<4;j++) acc[i][j]=0.f;
    for (int kk=0;kk<64;kk++){
        float a[4],b[4];
        #pragma unroll
        for(int i=0;i<4;i++) a[i]=sq[(r0+i)*P+kk];
        #pragma unroll
        for(int j=0;j<4;j++) b[j]=sW[kk*P+c0+j];
        #pragma unroll
        for(int i=0;i<4;i++) for(int j=0;j<4;j++) acc[i][j]+=a[i]*b[j];
    }
    #pragma unroll
    for(int i=0;i<4;i++) for(int j=0;j<4;j++){
        float z=acc[i][j];
        sh[(r0+i)*P+c0+j]=z*sigmf(z);
    }
    __syncthreads();
    for (int i=tid;i<4096;i+=256){
        int r=i>>6, c=i&63;
        sW[r*P+c]=w2[i]+u2[i];
    }
    __syncthreads();

    // y = h @ (w2+u2)
    #pragma unroll
    for(int i=0;i<4;i++) for(int j=0;j<4;j++) acc[i][j]=0.f;
    for (int kk=0;kk<64;kk++){
        float a[4],b[4];
        #pragma unroll
        for(int i=0;i<4;i++) a[i]=sh[(r0+i)*P+kk];
        #pragma unroll
        for(int j=0;j<4;j++) b[j]=sW[kk*P+c0+j];
        #pragma unroll
        for(int i=0;i<4;i++) for(int j=0;j<4;j++) acc[i][j]+=a[i]*b[j];
    }
    #pragma unroll
    for(int i=0;i<4;i++) for(int j=0;j<4;j++)
        sy[(r0+i)*P+c0+j]=acc[i][j];
    __syncthreads();

    // per-row rmsnorm over d, * (1+gamma) * gate
    int row = tid>>2, part = tid&3;
    float ssum=0.f;
    #pragma unroll
    for (int i=0;i<16;i++){ float v=sy[row*P+part*16+i]; ssum+=v*v; }
    ssum += __shfl_xor_sync(0xffffffffu, ssum, 1);
    ssum += __shfl_xor_sync(0xffffffffu, ssum, 2);
    float scn = rsqrtf(ssum*(1.0f/DDIM) + RMS_EPS);
    float gt  = g_gate[(size_t)bh*TT + ch*CCH + row];
    float* dst = g_vals + ((size_t)(bi*TT + ch*CCH + row))*DIMV + h*DDIM + part*16;
    #pragma unroll
    for (int i=0;i<16;i++)
        dst[i] = sy[row*P+part*16+i]*scn*(1.0f + gamma[h*DDIM+part*16+i])*gt;
}

// -------------------------------- launch ----------------------------------
extern "C" void kernel_launch(void* const* d_in, const int* in_sizes, int n_in,
                              void* d_out, int out_size){
    const float* seq   = (const float*)d_in[0];
    const float* w1    = (const float*)d_in[1];
    const float* w2    = (const float*)d_in[2];
    const float* Wq    = (const float*)d_in[3];
    const float* Wkv   = (const float*)d_in[4];
    const float* Wstep = (const float*)d_in[5];
    const float* Wmom  = (const float*)d_in[6];
    const float* Wdec  = (const float*)d_in[7];
    const float* Wgate = (const float*)d_in[8];
    const float* Wcmb  = (const float*)d_in[9];
    const float* gamma = (const float*)d_in[10];
    float* out = (float*)d_out;

    const int SMEM_GRADS = 6*64*65*(int)sizeof(float);   // 99840
    const int SMEM_RETR  = 4*64*65*(int)sizeof(float);   // 66560
    static bool attr_done = false;
    if (!attr_done){
        cudaFuncSetAttribute(k_grads,    cudaFuncAttributeMaxDynamicSharedMemorySize, SMEM_GRADS);
        cudaFuncSetAttribute(k_retrieve, cudaFuncAttributeMaxDynamicSharedMemorySize, SMEM_RETR);
        attr_done = true;
    }

    k_rmsnorm   <<<BB*TT, 128>>>(seq, out);
    k_lr_gate   <<<(BB*TT)/128, 256>>>(Wstep, Wgate);
    k_chunk_gates<<<BB*NCH, 256>>>(Wmom, Wdec);

    dim3 gkv(1024/128, (BB*TT)/128);
    k_sgemm<0><<<gkv, 256>>>(Wkv, nullptr, DIMV, 1024);
    dim3 gq(512/128, (BB*TT)/128);
    k_sgemm<1><<<gq, 256>>>(Wq, nullptr, DIMV, 512);

    k_grads<<<BHX*NCH, 256, SMEM_GRADS>>>(w1, w2);
    k_scan <<<dim3(BHX, 16), 256>>>();
    k_retrieve<<<BHX*NCH, 256, SMEM_RETR>>>(w1, w2, gamma);

    dim3 gc(512/128, (BB*TT)/128);
    k_sgemm<2><<<gc, 256>>>(Wcmb, out, DIMV, 512);
}